// round 2
// baseline (speedup 1.0000x reference)
#include <cuda_runtime.h>
#include <math.h>

#define N_FEAT 7
#define FUZZ   2187
#define MID    512
#define NCLS   10
#define BATCH  4096
#define T21    21
#define NCHUNK 27          // k-chunks for wei reduction
#define CHUNK_K 81         // k per chunk (27*81 = 2187)
#define COLT   9           // column tiles of 256
#define WCH    16          // j-chunks for W23 partials

// ---- device scratch (no allocations allowed) ----
__device__ float g_partialS[NCHUNK * T21 * FUZZ];  // ~5 MB
__device__ float g_S[T21 * FUZZ];
__device__ float g_rowS[T21];
__device__ float g_T1[T21 * MID];
__device__ float g_r1[MID];
__device__ float g_T3[NCLS * T21];
__device__ float g_r3[NCLS];
__device__ float g_c3[NCLS];
__device__ float g_partW[WCH * NCLS * MID];
__device__ float g_W23[NCLS * MID];
__device__ float g_G[NCLS * T21];
__device__ float g_q[NCLS];
__device__ float g_cc2[NCLS];

// ============================================================
// Stage 1: partial S over 27 k-chunks (1 FADD per load)  +  W23 partials
// ============================================================
__global__ void __launch_bounds__(256) k_stage1(
        const float* __restrict__ wei,
        const float* __restrict__ W2,
        const float* __restrict__ W3) {
    int b   = blockIdx.x;
    int tid = threadIdx.x;

    if (b < NCHUNK * COLT) {
        int colTile = b % COLT;
        int chunk   = b / COLT;
        int j  = colTile * 256 + tid;
        bool ok = (j < FUZZ);
        int jj = ok ? j : 0;

        // digits of chunk (base 3) select the slot for f = 0..2 (block-constant)
        int m0 = (chunk / 9) % 3;
        int m1 = (chunk / 3) % 3;
        int m2 =  chunk      % 3;

        float a0 = 0.f, a1 = 0.f, a2 = 0.f;
        float a3[3] = {0.f, 0.f, 0.f};
        float a4[3] = {0.f, 0.f, 0.f};
        float a5[3] = {0.f, 0.f, 0.f};
        float a6[3] = {0.f, 0.f, 0.f};

        const float* base = wei + (size_t)(chunk * CHUNK_K) * 7 * FUZZ + jj;
#pragma unroll
        for (int g = 0; g < 3; g++) {
#pragma unroll
            for (int q = 0; q < 27; q++) {
                const float* rp = base + (size_t)(g * 27 + q) * 7 * FUZZ;
                a0            += __ldg(rp + 0 * FUZZ);
                a1            += __ldg(rp + 1 * FUZZ);
                a2            += __ldg(rp + 2 * FUZZ);
                a3[g]         += __ldg(rp + 3 * FUZZ);   // (k/27)%3 == g
                a4[(q/9)%3]   += __ldg(rp + 4 * FUZZ);
                a5[(q/3)%3]   += __ldg(rp + 5 * FUZZ);
                a6[q%3]       += __ldg(rp + 6 * FUZZ);
            }
        }
        if (ok) {
            float outv[T21];
#pragma unroll
            for (int m = 0; m < 3; m++) {
                outv[0*3+m] = (m == m0) ? a0 : 0.f;
                outv[1*3+m] = (m == m1) ? a1 : 0.f;
                outv[2*3+m] = (m == m2) ? a2 : 0.f;
                outv[3*3+m] = a3[m];
                outv[4*3+m] = a4[m];
                outv[5*3+m] = a5[m];
                outv[6*3+m] = a6[m];
            }
            float* dst = g_partialS + (size_t)chunk * (T21 * FUZZ) + j;
#pragma unroll
            for (int t = 0; t < T21; t++) dst[t * FUZZ] = outv[t];
        }
    } else {
        // ---- W23 partial: W23[n,i] = sum_j W3[n,j] * W2[j,i] ----
        int b2    = b - NCHUNK * COLT;
        int itile = b2 & 1;
        int chunk = b2 >> 1;
        int i  = itile * 256 + tid;
        int j0 = chunk * 137;
        int j1 = min(FUZZ, j0 + 137);

        float acc[NCLS];
#pragma unroll
        for (int n = 0; n < NCLS; n++) acc[n] = 0.f;

        for (int j = j0; j < j1; j++) {
            float w2 = __ldg(W2 + j * MID + i);
#pragma unroll
            for (int n = 0; n < NCLS; n++)
                acc[n] += __ldg(W3 + n * FUZZ + j) * w2;
        }
#pragma unroll
        for (int n = 0; n < NCLS; n++)
            g_partW[chunk * (NCLS * MID) + n * MID + i] = acc[n];
    }
}

// ============================================================
// Stage 2: reduce S partials (fixed order -> deterministic)
// ============================================================
__global__ void k_reduceS() {
    int idx = blockIdx.x * 256 + threadIdx.x;
    if (idx < T21 * FUZZ) {
        float s = 0.f;
#pragma unroll
        for (int c = 0; c < NCHUNK; c++)
            s += g_partialS[(size_t)c * (T21 * FUZZ) + idx];
        g_S[idx] = s;
    }
}

// ============================================================
// Stage 3: T1 (warp-per-column), T3/r3/c3, rowS, W23 reduce
// ============================================================
__global__ void __launch_bounds__(256) k_stage3(
        const float* __restrict__ W1,
        const float* __restrict__ W3,
        const float* __restrict__ b2) {
    __shared__ float sm[23 * 8];
    int b    = blockIdx.x;
    int tid  = threadIdx.x;
    int lane = tid & 31;
    int warp = tid >> 5;

    if (b < MID / 8) {
        // T1[t][i], r1[i] : warp-per-i, 8 i per block (S reads L1-shared)
        int i = b * 8 + warp;
        float acc[22];
#pragma unroll
        for (int t = 0; t < 22; t++) acc[t] = 0.f;
        for (int j = lane; j < FUZZ; j += 32) {
            float w = __ldg(W1 + i * FUZZ + j);
#pragma unroll
            for (int t = 0; t < T21; t++) acc[t] += w * __ldg(&g_S[t * FUZZ + j]);
            acc[21] += w;
        }
#pragma unroll
        for (int t = 0; t < 22; t++) {
            for (int off = 16; off; off >>= 1)
                acc[t] += __shfl_down_sync(0xffffffffu, acc[t], off);
        }
        if (lane < T21)       g_T1[lane * MID + i] = __shfl_sync(0xffffffffu, acc[0], 0);
        // broadcast each reduced value from lane0 individually:
        if (lane == 0) {
#pragma unroll
            for (int t = 0; t < T21; t++) g_T1[t * MID + i] = acc[t];
            g_r1[i] = acc[21];
        }
    } else if (b < MID / 8 + NCLS) {
        // T3[n][t], r3[n], c3[n]
        int n = b - MID / 8;
        float acc[23];
#pragma unroll
        for (int t = 0; t < 23; t++) acc[t] = 0.f;
        for (int j = tid; j < FUZZ; j += 256) {
            float w3 = __ldg(W3 + n * FUZZ + j);
#pragma unroll
            for (int t = 0; t < T21; t++) acc[t] += w3 * g_S[t * FUZZ + j];
            acc[21] += w3;
            acc[22] += w3 * __ldg(b2 + j);
        }
#pragma unroll
        for (int t = 0; t < 23; t++) {
            for (int off = 16; off; off >>= 1)
                acc[t] += __shfl_down_sync(0xffffffffu, acc[t], off);
            if (lane == 0) sm[t * 8 + warp] = acc[t];
        }
        __syncthreads();
        if (tid < 23) {
            float s = 0.f;
#pragma unroll
            for (int w = 0; w < 8; w++) s += sm[tid * 8 + w];
            if (tid < T21)       g_T3[n * T21 + tid] = s;
            else if (tid == 21)  g_r3[n] = s;
            else                 g_c3[n] = s;
        }
    } else if (b < MID / 8 + NCLS + T21) {
        // rowS[t]
        int t = b - MID / 8 - NCLS;
        float s = 0.f;
        for (int j = tid; j < FUZZ; j += 256) s += g_S[t * FUZZ + j];
        for (int off = 16; off; off >>= 1)
            s += __shfl_down_sync(0xffffffffu, s, off);
        if (lane == 0) sm[warp] = s;
        __syncthreads();
        if (tid == 0) {
            float tot = 0.f;
#pragma unroll
            for (int w = 0; w < 8; w++) tot += sm[w];
            g_rowS[t] = tot;
        }
    } else {
        // W23 reduce
        for (int e = tid; e < NCLS * MID; e += 256) {
            float s = 0.f;
#pragma unroll
            for (int c = 0; c < WCH; c++) s += g_partW[c * (NCLS * MID) + e];
            g_W23[e] = s;
        }
    }
}

// ============================================================
// Stage 3b: fold MID dimension out: G, q, cc2  (warp per dot)
// ============================================================
__global__ void __launch_bounds__(256) k_prep(const float* __restrict__ b1,
                                              const float* __restrict__ b3) {
    int lane = threadIdx.x & 31;
    int gw   = blockIdx.x * 8 + (threadIdx.x >> 5);

    if (gw < NCLS * T21) {
        int n = gw / T21, t = gw % T21;
        float s = 0.f;
#pragma unroll
        for (int k = 0; k < MID / 32; k++) {
            int i = k * 32 + lane;
            s += g_W23[n * MID + i] * g_T1[t * MID + i];
        }
        for (int off = 16; off; off >>= 1)
            s += __shfl_down_sync(0xffffffffu, s, off);
        if (lane == 0) g_G[n * T21 + t] = s + g_T3[n * T21 + t];
    } else if (gw < NCLS * T21 + NCLS) {
        int n = gw - NCLS * T21;
        float s = 0.f;
#pragma unroll
        for (int k = 0; k < MID / 32; k++) {
            int i = k * 32 + lane;
            s += g_W23[n * MID + i] * g_r1[i];
        }
        for (int off = 16; off; off >>= 1)
            s += __shfl_down_sync(0xffffffffu, s, off);
        if (lane == 0) g_q[n] = s + g_r3[n];
    } else if (gw < NCLS * T21 + 2 * NCLS) {
        int n = gw - NCLS * T21 - NCLS;
        float s = 0.f;
#pragma unroll
        for (int k = 0; k < MID / 32; k++) {
            int i = k * 32 + lane;
            s += g_W23[n * MID + i] * __ldg(b1 + i);
        }
        for (int off = 16; off; off >>= 1)
            s += __shfl_down_sync(0xffffffffu, s, off);
        if (lane == 0) g_cc2[n] = s + g_c3[n] + __ldg(b3 + n);
    }
}

// ============================================================
// Stage 4: one thread per batch row (≈250 FMA + 21 exp each)
// ============================================================
__global__ void __launch_bounds__(32) k_main(
        const float* __restrict__ x,  const float* __restrict__ cc,
        const float* __restrict__ bb, const float* __restrict__ bais,
        float* __restrict__ out) {
    __shared__ float sG[NCLS * T21];
    __shared__ float sq[NCLS];
    __shared__ float scc[NCLS];
    __shared__ float srowS[T21];
    __shared__ float sc[T21];
    __shared__ float sib[T21];

    int tid = threadIdx.x;
    for (int e = tid; e < NCLS * T21; e += 32) sG[e] = g_G[e];
    if (tid < NCLS) { sq[tid] = g_q[tid]; scc[tid] = g_cc2[tid]; }
    if (tid < T21) {
        srowS[tid] = g_rowS[tid];
        sc[tid] = __ldg(cc + tid);
        float bw = __ldg(bb + tid);
        sib[tid] = 1.0f / (bw * bw);
    }
    float bv = __ldg(bais);
    __syncthreads();

    int row = blockIdx.x * 32 + tid;
    float xv[N_FEAT];
#pragma unroll
    for (int f = 0; f < N_FEAT; f++) xv[f] = __ldg(x + row * N_FEAT + f);

    float u[T21];
    float rs = (float)FUZZ * bv;
#pragma unroll
    for (int t = 0; t < T21; t++) {
        float d = xv[t / 3] - sc[t];
        u[t] = expf(-d * d * sib[t]);
        rs += u[t] * srowS[t];
    }
    float inv = 1.0f / rs;

#pragma unroll
    for (int n = 0; n < NCLS; n++) {
        float s = bv * sq[n];
#pragma unroll
        for (int t = 0; t < T21; t++) s += u[t] * sG[n * T21 + t];
        float h = inv * s + scc[n];
        out[row * NCLS + n] = (h >= 0.f) ? h : 0.2f * h;
    }
}

// ============================================================
extern "C" void kernel_launch(void* const* d_in, const int* in_sizes, int n_in,
                              void* d_out, int out_size) {
    const float* x    = (const float*)d_in[0];
    const float* c    = (const float*)d_in[1];
    const float* b    = (const float*)d_in[2];
    const float* wei  = (const float*)d_in[3];
    const float* bais = (const float*)d_in[4];
    const float* W1   = (const float*)d_in[5];
    const float* b1   = (const float*)d_in[6];
    const float* W2   = (const float*)d_in[7];
    const float* b2   = (const float*)d_in[8];
    const float* W3   = (const float*)d_in[9];
    const float* b3   = (const float*)d_in[10];
    float* out = (float*)d_out;

    k_stage1<<<NCHUNK * COLT + 2 * WCH, 256>>>(wei, W2, W3);
    k_reduceS<<<(T21 * FUZZ + 255) / 256, 256>>>();
    k_stage3<<<MID / 8 + NCLS + T21 + 1, 256>>>(W1, W3, b2);
    k_prep<<<30, 256>>>(b1, b3);
    k_main<<<BATCH / 32, 32>>>(x, c, b, bais, out);
}

// round 3
// speedup vs baseline: 1.1201x; 1.1201x over previous
#include <cuda_runtime.h>
#include <math.h>

#define N_FEAT 7
#define FUZZ   2187
#define MID    512
#define NCLS   10
#define BATCH  4096
#define T21    21
#define NCHUNK 81          // k-chunks for wei reduction
#define CHUNK_K 27         // k per chunk (81*27 = 2187)
#define COLT   9           // column tiles of 256
#define NSLOT  13          // compact partial slots per chunk
#define WCH    16          // j-chunks for W23 partials

// ---- device scratch (no allocations allowed) ----
__device__ float g_p[(size_t)NCHUNK * NSLOT * FUZZ];   // 9.2 MB compact partials
__device__ float g_S[T21 * FUZZ];
__device__ float g_rowS[T21];
__device__ float g_T1[T21 * MID];
__device__ float g_r1[MID];
__device__ float g_T3[NCLS * T21];
__device__ float g_r3[NCLS];
__device__ float g_c3[NCLS];
__device__ float g_partW[WCH * NCLS * MID];
__device__ float g_W23[NCLS * MID];
__device__ float g_G[NCLS * T21];
__device__ float g_q[NCLS];
__device__ float g_cc2[NCLS];

// ============================================================
// Stage 1: compact S partials (13 slots, 1 FADD/load) + W23 partials
//   k = chunk*27 + q ;  digit(f) = (k / 3^(6-f)) % 3
//   f=0..3 digits are block-constant; f=4..6 digits compile-time in q
// ============================================================
__global__ void __launch_bounds__(256, 3) k_stage1(
        const float* __restrict__ wei,
        const float* __restrict__ W2,
        const float* __restrict__ W3) {
    int b   = blockIdx.x;
    int tid = threadIdx.x;

    if (b < NCHUNK * COLT) {
        int colTile = b % COLT;
        int chunk   = b / COLT;
        int j  = colTile * 256 + tid;
        bool ok = (j < FUZZ);
        int jj = ok ? j : 0;

        float s0 = 0.f, s1 = 0.f, s2 = 0.f, s3 = 0.f;
        float a4[3] = {0.f, 0.f, 0.f};
        float a5[3] = {0.f, 0.f, 0.f};
        float a6[3] = {0.f, 0.f, 0.f};

        const float* base = wei + (size_t)(chunk * CHUNK_K) * 7 * FUZZ + jj;
#pragma unroll
        for (int q = 0; q < CHUNK_K; q++) {
            const float* rp = base + (size_t)q * 7 * FUZZ;
            s0          += __ldg(rp + 0 * FUZZ);
            s1          += __ldg(rp + 1 * FUZZ);
            s2          += __ldg(rp + 2 * FUZZ);
            s3          += __ldg(rp + 3 * FUZZ);
            a4[q / 9]   += __ldg(rp + 4 * FUZZ);
            a5[(q/3)%3] += __ldg(rp + 5 * FUZZ);
            a6[q % 3]   += __ldg(rp + 6 * FUZZ);
        }
        if (ok) {
            float* dst = g_p + (size_t)chunk * (NSLOT * FUZZ) + j;
            dst[0 * FUZZ] = s0;
            dst[1 * FUZZ] = s1;
            dst[2 * FUZZ] = s2;
            dst[3 * FUZZ] = s3;
#pragma unroll
            for (int m = 0; m < 3; m++) {
                dst[(4 + m)  * FUZZ] = a4[m];
                dst[(7 + m)  * FUZZ] = a5[m];
                dst[(10 + m) * FUZZ] = a6[m];
            }
        }
    } else {
        // ---- W23 partial: W23[n,i] = sum_j W3[n,j] * W2[j,i] ----
        int b2    = b - NCHUNK * COLT;
        int itile = b2 & 1;
        int chunk = b2 >> 1;
        int i  = itile * 256 + tid;
        int j0 = chunk * 137;
        int j1 = min(FUZZ, j0 + 137);

        float acc[NCLS];
#pragma unroll
        for (int n = 0; n < NCLS; n++) acc[n] = 0.f;

        for (int j = j0; j < j1; j++) {
            float w2 = __ldg(W2 + j * MID + i);
#pragma unroll
            for (int n = 0; n < NCLS; n++)
                acc[n] += __ldg(W3 + n * FUZZ + j) * w2;
        }
#pragma unroll
        for (int n = 0; n < NCLS; n++)
            g_partW[chunk * (NCLS * MID) + n * MID + i] = acc[n];
    }
}

// ============================================================
// Stage 2: reduce compact partials into S (fixed order)
//   t = f*3+m.  f<4: only chunks with digit_f(chunk)==m contribute (slot f)
//               f>=4: all chunks, slot 4 + (f-4)*3 + m
// ============================================================
__global__ void k_reduceS() {
    int idx = blockIdx.x * 256 + threadIdx.x;
    if (idx >= T21 * FUZZ) return;
    int t = idx / FUZZ, j = idx % FUZZ;
    int f = t / 3, m = t % 3;

    float s = 0.f;
    if (f < 4) {
        // D = 3^(3-f); chunks c with (c/D)%3 == m
        int D = (f == 0) ? 27 : (f == 1) ? 9 : (f == 2) ? 3 : 1;
        int nHi = NCHUNK / (3 * D);
        for (int hi = 0; hi < nHi; hi++)
            for (int lo = 0; lo < D; lo++) {
                int c = hi * 3 * D + m * D + lo;
                s += g_p[(size_t)c * (NSLOT * FUZZ) + f * FUZZ + j];
            }
    } else {
        int slot = 4 + (f - 4) * 3 + m;
#pragma unroll 3
        for (int c = 0; c < NCHUNK; c++)
            s += g_p[(size_t)c * (NSLOT * FUZZ) + slot * FUZZ + j];
    }
    g_S[idx] = s;
}

// ============================================================
// Stage 3: T1 (warp-per-column), T3/r3/c3, rowS, W23 reduce
// ============================================================
__global__ void __launch_bounds__(256) k_stage3(
        const float* __restrict__ W1,
        const float* __restrict__ W3,
        const float* __restrict__ b2) {
    __shared__ float sm[23 * 8];
    int b    = blockIdx.x;
    int tid  = threadIdx.x;
    int lane = tid & 31;
    int warp = tid >> 5;

    if (b < MID / 8) {
        // T1[t][i], r1[i] : warp-per-i, 8 i per block (S reads L1-shared)
        int i = b * 8 + warp;
        float acc[22];
#pragma unroll
        for (int t = 0; t < 22; t++) acc[t] = 0.f;
        for (int j = lane; j < FUZZ; j += 32) {
            float w = __ldg(W1 + i * FUZZ + j);
#pragma unroll
            for (int t = 0; t < T21; t++) acc[t] += w * __ldg(&g_S[t * FUZZ + j]);
            acc[21] += w;
        }
#pragma unroll
        for (int t = 0; t < 22; t++)
            for (int off = 16; off; off >>= 1)
                acc[t] += __shfl_down_sync(0xffffffffu, acc[t], off);
        if (lane == 0) {
#pragma unroll
            for (int t = 0; t < T21; t++) g_T1[t * MID + i] = acc[t];
            g_r1[i] = acc[21];
        }
    } else if (b < MID / 8 + NCLS) {
        // T3[n][t], r3[n], c3[n]
        int n = b - MID / 8;
        float acc[23];
#pragma unroll
        for (int t = 0; t < 23; t++) acc[t] = 0.f;
        for (int j = tid; j < FUZZ; j += 256) {
            float w3 = __ldg(W3 + n * FUZZ + j);
#pragma unroll
            for (int t = 0; t < T21; t++) acc[t] += w3 * g_S[t * FUZZ + j];
            acc[21] += w3;
            acc[22] += w3 * __ldg(b2 + j);
        }
#pragma unroll
        for (int t = 0; t < 23; t++) {
            for (int off = 16; off; off >>= 1)
                acc[t] += __shfl_down_sync(0xffffffffu, acc[t], off);
            if (lane == 0) sm[t * 8 + warp] = acc[t];
        }
        __syncthreads();
        if (tid < 23) {
            float s = 0.f;
#pragma unroll
            for (int w = 0; w < 8; w++) s += sm[tid * 8 + w];
            if (tid < T21)       g_T3[n * T21 + tid] = s;
            else if (tid == 21)  g_r3[n] = s;
            else                 g_c3[n] = s;
        }
    } else if (b < MID / 8 + NCLS + T21) {
        // rowS[t]
        int t = b - MID / 8 - NCLS;
        float s = 0.f;
        for (int j = tid; j < FUZZ; j += 256) s += g_S[t * FUZZ + j];
        for (int off = 16; off; off >>= 1)
            s += __shfl_down_sync(0xffffffffu, s, off);
        if (lane == 0) sm[warp] = s;
        __syncthreads();
        if (tid == 0) {
            float tot = 0.f;
#pragma unroll
            for (int w = 0; w < 8; w++) tot += sm[w];
            g_rowS[t] = tot;
        }
    } else {
        // W23 reduce
        for (int e = tid; e < NCLS * MID; e += 256) {
            float s = 0.f;
#pragma unroll
            for (int c = 0; c < WCH; c++) s += g_partW[c * (NCLS * MID) + e];
            g_W23[e] = s;
        }
    }
}

// ============================================================
// Stage 3b: fold MID out: G = T3 + W23*T1^T, q = r3 + W23*r1,
//           cc2 = c3 + b3 + W23*b1       (warp per dot product)
// ============================================================
__global__ void __launch_bounds__(256) k_prep(const float* __restrict__ b1,
                                              const float* __restrict__ b3) {
    int lane = threadIdx.x & 31;
    int gw   = blockIdx.x * 8 + (threadIdx.x >> 5);

    if (gw < NCLS * T21) {
        int n = gw / T21, t = gw % T21;
        float s = 0.f;
#pragma unroll
        for (int k = 0; k < MID / 32; k++) {
            int i = k * 32 + lane;
            s += g_W23[n * MID + i] * g_T1[t * MID + i];
        }
        for (int off = 16; off; off >>= 1)
            s += __shfl_down_sync(0xffffffffu, s, off);
        if (lane == 0) g_G[n * T21 + t] = s + g_T3[n * T21 + t];
    } else if (gw < NCLS * T21 + NCLS) {
        int n = gw - NCLS * T21;
        float s = 0.f;
#pragma unroll
        for (int k = 0; k < MID / 32; k++) {
            int i = k * 32 + lane;
            s += g_W23[n * MID + i] * g_r1[i];
        }
        for (int off = 16; off; off >>= 1)
            s += __shfl_down_sync(0xffffffffu, s, off);
        if (lane == 0) g_q[n] = s + g_r3[n];
    } else if (gw < NCLS * T21 + 2 * NCLS) {
        int n = gw - NCLS * T21 - NCLS;
        float s = 0.f;
#pragma unroll
        for (int k = 0; k < MID / 32; k++) {
            int i = k * 32 + lane;
            s += g_W23[n * MID + i] * __ldg(b1 + i);
        }
        for (int off = 16; off; off >>= 1)
            s += __shfl_down_sync(0xffffffffu, s, off);
        if (lane == 0) g_cc2[n] = s + g_c3[n] + __ldg(b3 + n);
    }
}

// ============================================================
// Stage 4: one thread per batch row (~250 FMA + 21 exp each)
// ============================================================
__global__ void __launch_bounds__(256) k_main(
        const float* __restrict__ x,  const float* __restrict__ cc,
        const float* __restrict__ bb, const float* __restrict__ bais,
        float* __restrict__ out) {
    __shared__ float sG[NCLS * T21];
    __shared__ float sq[NCLS];
    __shared__ float scc[NCLS];
    __shared__ float srowS[T21];
    __shared__ float sc[T21];
    __shared__ float sib[T21];

    int tid = threadIdx.x;
    for (int e = tid; e < NCLS * T21; e += 256) sG[e] = g_G[e];
    if (tid < NCLS) { sq[tid] = g_q[tid]; scc[tid] = g_cc2[tid]; }
    if (tid < T21) {
        srowS[tid] = g_rowS[tid];
        sc[tid] = __ldg(cc + tid);
        float bw = __ldg(bb + tid);
        sib[tid] = 1.0f / (bw * bw);
    }
    float bv = __ldg(bais);
    __syncthreads();

    int row = blockIdx.x * 256 + tid;
    float xv[N_FEAT];
#pragma unroll
    for (int f = 0; f < N_FEAT; f++) xv[f] = __ldg(x + row * N_FEAT + f);

    float u[T21];
    float rs = (float)FUZZ * bv;
#pragma unroll
    for (int t = 0; t < T21; t++) {
        float d = xv[t / 3] - sc[t];
        u[t] = expf(-d * d * sib[t]);
        rs += u[t] * srowS[t];
    }
    float inv = 1.0f / rs;

#pragma unroll
    for (int n = 0; n < NCLS; n++) {
        float s = bv * sq[n];
#pragma unroll
        for (int t = 0; t < T21; t++) s += u[t] * sG[n * T21 + t];
        float h = inv * s + scc[n];
        out[row * NCLS + n] = (h >= 0.f) ? h : 0.2f * h;
    }
}

// ============================================================
extern "C" void kernel_launch(void* const* d_in, const int* in_sizes, int n_in,
                              void* d_out, int out_size) {
    const float* x    = (const float*)d_in[0];
    const float* c    = (const float*)d_in[1];
    const float* b    = (const float*)d_in[2];
    const float* wei  = (const float*)d_in[3];
    const float* bais = (const float*)d_in[4];
    const float* W1   = (const float*)d_in[5];
    const float* b1   = (const float*)d_in[6];
    const float* W2   = (const float*)d_in[7];
    const float* b2   = (const float*)d_in[8];
    const float* W3   = (const float*)d_in[9];
    const float* b3   = (const float*)d_in[10];
    float* out = (float*)d_out;

    k_stage1<<<NCHUNK * COLT + 2 * WCH, 256>>>(wei, W2, W3);
    k_reduceS<<<(T21 * FUZZ + 255) / 256, 256>>>();
    k_stage3<<<MID / 8 + NCLS + T21 + 1, 256>>>(W1, W3, b2);
    k_prep<<<30, 256>>>(b1, b3);
    k_main<<<BATCH / 256, 256>>>(x, c, b, bais, out);
}